// round 9
// baseline (speedup 1.0000x reference)
#include <cuda_runtime.h>
#include <cuda_bf16.h>
#include <math.h>
#include <stdint.h>

#define NN 40000
#define NE 640000
#define DIM 128
#define NH 8
#define DH 16

typedef __nv_bfloat16 bf16;

// ---------------- scratch (device globals: allocation-free) ----------------
__device__ float g_Qh[(size_t)NN * DIM];
__device__ float g_Kh[(size_t)NN * DIM];
__device__ float g_Vh[(size_t)NN * DIM];
__device__ float g_lg[(size_t)NE * NH];
__device__ float g_den[(size_t)NN * NH];
__device__ float g_wV[(size_t)NN * DIM];
__device__ float g_rowV[(size_t)NN * DIM];
__device__ float g_v1[(size_t)NN * DIM];
__device__ float g_v2[(size_t)NN * DIM];
__device__ float g_s1[2 * DIM];
__device__ float g_s2[2 * DIM];
__device__ float g_se[2 * DIM];
// bf16 hi/lo pairs
__device__ bf16 g_ethi[(size_t)NE * DIM], g_etlo[(size_t)NE * DIM];
__device__ bf16 g_hatth[(size_t)NN * DIM], g_hattl[(size_t)NN * DIM];
__device__ bf16 g_hbnh[(size_t)NN * DIM],  g_hbnl[(size_t)NN * DIM];
__device__ bf16 g_h2ah[(size_t)NN * 2 * DIM], g_h2al[(size_t)NN * 2 * DIM];
__device__ bf16 g_wq_h[DIM * DIM], g_wq_l[DIM * DIM];
__device__ bf16 g_wk_h[DIM * DIM], g_wk_l[DIM * DIM];
__device__ bf16 g_wv_h[DIM * DIM], g_wv_l[DIM * DIM];
__device__ bf16 g_we_h[DIM * 2 * DIM], g_we_l[DIM * 2 * DIM];
__device__ bf16 g_woh_h[DIM * DIM], g_woh_l[DIM * DIM];
__device__ bf16 g_woe_h[DIM * DIM], g_woe_l[DIM * DIM];
__device__ bf16 g_w1_h[DIM * 2 * DIM], g_w1_l[DIM * 2 * DIM];
__device__ bf16 g_w2_h[2 * DIM * DIM], g_w2_l[2 * DIM * DIM];

static inline int cdiv(long long a, long long b) { return (int)((a + b - 1) / b); }

// ---------------- helpers ----------------
__device__ __forceinline__ uint32_t smem_u32(const void* p) {
    uint32_t a;
    asm("{ .reg .u64 t; cvta.to.shared.u64 t, %1; cvt.u32.u64 %0, t; }" : "=r"(a) : "l"(p));
    return a;
}
__device__ __forceinline__ void ldsm4(uint32_t (&r)[4], uint32_t addr) {
    asm volatile("ldmatrix.sync.aligned.m8n8.x4.shared.b16 {%0,%1,%2,%3}, [%4];"
                 : "=r"(r[0]), "=r"(r[1]), "=r"(r[2]), "=r"(r[3]) : "r"(addr));
}
__device__ __forceinline__ void ldsm4t(uint32_t (&r)[4], uint32_t addr) {
    asm volatile("ldmatrix.sync.aligned.m8n8.x4.trans.shared.b16 {%0,%1,%2,%3}, [%4];"
                 : "=r"(r[0]), "=r"(r[1]), "=r"(r[2]), "=r"(r[3]) : "r"(addr));
}
__device__ __forceinline__ void mma16816(float (&d)[4], const uint32_t (&a)[4], const uint32_t* b) {
    asm volatile("mma.sync.aligned.m16n8k16.row.col.f32.bf16.bf16.f32 "
                 "{%0,%1,%2,%3}, {%4,%5,%6,%7}, {%8,%9}, {%0,%1,%2,%3};"
                 : "+f"(d[0]), "+f"(d[1]), "+f"(d[2]), "+f"(d[3])
                 : "r"(a[0]), "r"(a[1]), "r"(a[2]), "r"(a[3]), "r"(b[0]), "r"(b[1]));
}
__device__ __forceinline__ uint32_t pack2(bf16 a, bf16 b) {
    return (uint32_t)__bfloat16_as_ushort(a) | ((uint32_t)__bfloat16_as_ushort(b) << 16);
}
__device__ __forceinline__ float2 up2(uint32_t u) {
    return make_float2(__bfloat162float(__ushort_as_bfloat16((unsigned short)(u & 0xffff))),
                       __bfloat162float(__ushort_as_bfloat16((unsigned short)(u >> 16))));
}
__device__ __forceinline__ void split4(float4 v, uint2& hi, uint2& lo) {
    bf16 hx = __float2bfloat16(v.x), hy = __float2bfloat16(v.y);
    bf16 hz = __float2bfloat16(v.z), hw = __float2bfloat16(v.w);
    hi = make_uint2(pack2(hx, hy), pack2(hz, hw));
    lo = make_uint2(pack2(__float2bfloat16(v.x - __bfloat162float(hx)),
                          __float2bfloat16(v.y - __bfloat162float(hy))),
                    pack2(__float2bfloat16(v.z - __bfloat162float(hz)),
                          __float2bfloat16(v.w - __bfloat162float(hw))));
}
__device__ __forceinline__ uint32_t packsplit(float a, float b, uint32_t& lo) {
    bf16 h0 = __float2bfloat16(a), h1 = __float2bfloat16(b);
    lo = pack2(__float2bfloat16(a - __bfloat162float(h0)),
               __float2bfloat16(b - __bfloat162float(h1)));
    return pack2(h0, h1);
}
__device__ __forceinline__ void cp16(uint32_t dst, const void* src, int sz) {
    asm volatile("cp.async.cg.shared.global [%0], [%1], 16, %2;" :: "r"(dst), "l"(src), "r"(sz));
}
#define CP_COMMIT() asm volatile("cp.async.commit_group;" ::: "memory")
#define CP_WAIT0()  asm volatile("cp.async.wait_group 0;" ::: "memory")
#define CP_WAIT1()  asm volatile("cp.async.wait_group 1;" ::: "memory")

__device__ __forceinline__ void red4(float* p, float a, float b, float c, float d) {
    asm volatile("red.global.add.v4.f32 [%0], {%1,%2,%3,%4};"
                 :: "l"(p), "f"(a), "f"(b), "f"(c), "f"(d) : "memory");
}
__device__ __forceinline__ void redf(float* p, float a) {
    asm volatile("red.global.add.f32 [%0], %1;" :: "l"(p), "f"(a) : "memory");
}

// ============ pair-A GEMM core: 128x128 tile, 256 thr, 2-stage pipe =========
#define STG    37888u
#define AHI_O  0u
#define ALO_O  10240u
#define BHI_O  20480u
#define BLO_O  29184u
#define SMB_TOTAL 75776

struct GemmCoreB {
    uint32_t sb;
    int tid, lid, wm, wn, m0, n0;
    float acc[4][4][4];

    __device__ __forceinline__ void init(uint8_t* smp, int bm, int bn) {
        sb = smem_u32(smp);
        tid = threadIdx.x; lid = tid & 31;
        int wid = tid >> 5;
        wm = wid >> 2; wn = wid & 3;
        m0 = bm * 128; n0 = bn * 128;
#pragma unroll
        for (int i = 0; i < 4; i++)
#pragma unroll
            for (int j = 0; j < 4; j++)
#pragma unroll
                for (int q = 0; q < 4; q++) acc[i][j][q] = 0.f;
    }
    __device__ __forceinline__ void stage(int buf, const bf16* Ahi, const bf16* Alo,
                                          const bf16* Whi, const bf16* Wlo,
                                          int M, int Ncols, int K, int kb) {
        uint32_t base = sb + (uint32_t)buf * STG;
#pragma unroll
        for (int i = 0; i < 2; i++) {
            int c = tid + i * 256;
            int row = c >> 2, gr = c & 3;
            bool ok = (m0 + row) < M;
            size_t go = (size_t)(ok ? m0 + row : 0) * K + kb + gr * 8;
            uint32_t d = base + (uint32_t)row * 80 + (uint32_t)gr * 16;
            cp16(d + AHI_O, Ahi + go, ok ? 16 : 0);
            cp16(d + ALO_O, Alo + go, ok ? 16 : 0);
        }
#pragma unroll
        for (int i = 0; i < 2; i++) {
            int c = tid + i * 256;
            int k = c >> 4, gr = c & 15;
            size_t go = (size_t)(kb + k) * Ncols + n0 + gr * 8;
            uint32_t d = base + (uint32_t)k * 272 + (uint32_t)gr * 16;
            cp16(d + BHI_O, Whi + go, 16);
            cp16(d + BLO_O, Wlo + go, 16);
        }
        CP_COMMIT();
    }
    __device__ __forceinline__ void compute(int buf) {
        uint32_t base = sb + (uint32_t)buf * STG;
#pragma unroll
        for (int ks = 0; ks < 32; ks += 16) {
            uint32_t bhi[4][2], blo[4][2];
            const uint32_t brow = (uint32_t)(ks + (lid & 15)) * 272 + (uint32_t)((lid >> 4) * 16);
#pragma unroll
            for (int p = 0; p < 2; p++) {
                uint32_t baddr = base + brow + (uint32_t)(wn * 32 + p * 16) * 2;
                uint32_t r[4];
                ldsm4t(r, baddr + BHI_O);
                bhi[2 * p][0] = r[0]; bhi[2 * p][1] = r[1];
                bhi[2 * p + 1][0] = r[2]; bhi[2 * p + 1][1] = r[3];
                ldsm4t(r, baddr + BLO_O);
                blo[2 * p][0] = r[0]; blo[2 * p][1] = r[1];
                blo[2 * p + 1][0] = r[2]; blo[2 * p + 1][1] = r[3];
            }
            const uint32_t arow = (uint32_t)(wm * 64 + (lid & 15)) * 80
                                + (uint32_t)ks * 2 + (uint32_t)(lid >> 4) * 16;
#pragma unroll
            for (int mt = 0; mt < 4; mt++) {
                uint32_t aaddr = base + arow + (uint32_t)mt * (16 * 80);
                uint32_t ahi4[4], alo4[4];
                ldsm4(ahi4, aaddr + AHI_O);
                ldsm4(alo4, aaddr + ALO_O);
#pragma unroll
                for (int nt = 0; nt < 4; nt++) {
                    mma16816(acc[mt][nt], ahi4, bhi[nt]);
                    mma16816(acc[mt][nt], ahi4, blo[nt]);
                    mma16816(acc[mt][nt], alo4, bhi[nt]);
                }
            }
        }
    }
    __device__ __forceinline__ void run(const bf16* Ahi, const bf16* Alo,
                                        const bf16* Whi, const bf16* Wlo,
                                        int M, int Ncols, int K) {
        const int nch = K >> 5;
        stage(0, Ahi, Alo, Whi, Wlo, M, Ncols, K, 0);
        if (nch > 1) stage(1, Ahi, Alo, Whi, Wlo, M, Ncols, K, 32);
        for (int i = 0; i < nch; i++) {
            if (i == nch - 1) { CP_WAIT0(); } else { CP_WAIT1(); }
            __syncthreads();
            compute(i & 1);
            if (i + 2 < nch) {
                __syncthreads();
                stage(i & 1, Ahi, Alo, Whi, Wlo, M, Ncols, K, (i + 2) * 32);
            }
        }
    }
};

// ============ fp32-A GEMM core: stages fp32 A, converts to hi/lo in smem ====
#define FSTG   56320u
#define SGA_O  0u
#define FAHI_O 18432u
#define FALO_O 28672u
#define FBHI_O 38912u
#define FBLO_O 47616u
#define SMF_TOTAL 112640

struct GemmCoreF {
    uint32_t sb;
    int tid, lid, wm, wn, m0, n0;
    float acc[4][4][4];

    __device__ __forceinline__ void init(uint8_t* smp, int bm, int bn) {
        sb = smem_u32(smp);
        tid = threadIdx.x; lid = tid & 31;
        int wid = tid >> 5;
        wm = wid >> 2; wn = wid & 3;
        m0 = bm * 128; n0 = bn * 128;
#pragma unroll
        for (int i = 0; i < 4; i++)
#pragma unroll
            for (int j = 0; j < 4; j++)
#pragma unroll
                for (int q = 0; q < 4; q++) acc[i][j][q] = 0.f;
    }
    __device__ __forceinline__ void stage(int buf, const float* A,
                                          const bf16* Whi, const bf16* Wlo,
                                          int M, int Ncols, int K, int kb) {
        uint32_t base = sb + (uint32_t)buf * FSTG;
#pragma unroll
        for (int i = 0; i < 4; i++) {
            int c = tid + i * 256;
            int row = c >> 3, kq = c & 7;
            bool ok = (m0 + row) < M;
            const float* src = A + (size_t)(ok ? m0 + row : 0) * K + kb + kq * 4;
            cp16(base + SGA_O + (uint32_t)row * 144 + (uint32_t)kq * 16, src, ok ? 16 : 0);
        }
#pragma unroll
        for (int i = 0; i < 2; i++) {
            int c = tid + i * 256;
            int k = c >> 4, gr = c & 15;
            size_t go = (size_t)(kb + k) * Ncols + n0 + gr * 8;
            uint32_t d = base + (uint32_t)k * 272 + (uint32_t)gr * 16;
            cp16(d + FBHI_O, Whi + go, 16);
            cp16(d + FBLO_O, Wlo + go, 16);
        }
        CP_COMMIT();
    }
    __device__ __forceinline__ void convertA(int buf, uint8_t* smp) {
        uint32_t boff = (uint32_t)buf * FSTG;
#pragma unroll
        for (int i = 0; i < 4; i++) {
            int c = tid + i * 256;
            int row = c >> 3, kq = c & 7;
            float4 v = *(const float4*)(smp + boff + SGA_O + (uint32_t)row * 144 + (uint32_t)kq * 16);
            uint2 hi, lo;
            split4(v, hi, lo);
            uint32_t off = boff + (uint32_t)row * 80 + (uint32_t)kq * 8;
            *(uint2*)(smp + FAHI_O + off) = hi;
            *(uint2*)(smp + FALO_O + off) = lo;
        }
    }
    __device__ __forceinline__ void compute(int buf) {
        uint32_t base = sb + (uint32_t)buf * FSTG;
#pragma unroll
        for (int ks = 0; ks < 32; ks += 16) {
            uint32_t bhi[4][2], blo[4][2];
            const uint32_t brow = (uint32_t)(ks + (lid & 15)) * 272 + (uint32_t)((lid >> 4) * 16);
#pragma unroll
            for (int p = 0; p < 2; p++) {
                uint32_t baddr = base + brow + (uint32_t)(wn * 32 + p * 16) * 2;
                uint32_t r[4];
                ldsm4t(r, baddr + FBHI_O);
                bhi[2 * p][0] = r[0]; bhi[2 * p][1] = r[1];
                bhi[2 * p + 1][0] = r[2]; bhi[2 * p + 1][1] = r[3];
                ldsm4t(r, baddr + FBLO_O);
                blo[2 * p][0] = r[0]; blo[2 * p][1] = r[1];
                blo[2 * p + 1][0] = r[2]; blo[2 * p + 1][1] = r[3];
            }
            const uint32_t arow = (uint32_t)(wm * 64 + (lid & 15)) * 80
                                + (uint32_t)ks * 2 + (uint32_t)(lid >> 4) * 16;
#pragma unroll
            for (int mt = 0; mt < 4; mt++) {
                uint32_t aaddr = base + arow + (uint32_t)mt * (16 * 80);
                uint32_t ahi4[4], alo4[4];
                ldsm4(ahi4, aaddr + FAHI_O);
                ldsm4(alo4, aaddr + FALO_O);
#pragma unroll
                for (int nt = 0; nt < 4; nt++) {
                    mma16816(acc[mt][nt], ahi4, bhi[nt]);
                    mma16816(acc[mt][nt], ahi4, blo[nt]);
                    mma16816(acc[mt][nt], alo4, bhi[nt]);
                }
            }
        }
    }
    __device__ __forceinline__ void run(uint8_t* smp, const float* A,
                                        const bf16* Whi, const bf16* Wlo,
                                        int M, int Ncols, int K) {
        const int nch = K >> 5;
        stage(0, A, Whi, Wlo, M, Ncols, K, 0);
        if (nch > 1) stage(1, A, Whi, Wlo, M, Ncols, K, 32);
        for (int i = 0; i < nch; i++) {
            if (i == nch - 1) { CP_WAIT0(); } else { CP_WAIT1(); }
            __syncthreads();
            convertA(i & 1, smp);
            __syncthreads();
            compute(i & 1);
            if (i + 2 < nch) {
                __syncthreads();
                stage(i & 1, A, Whi, Wlo, M, Ncols, K, (i + 2) * 32);
            }
        }
    }
};

// ---------------- generic pair-A GEMM ----------------
// RESMODE 0=none 1=f32 2=bf16pair; OUTMODE 0=f32 1=pair; STATS: fused col sums
template <int RESMODE, int OUTMODE, bool RELU, bool STATS>
__global__ void __launch_bounds__(256, 2)
mma_gemmB(const bf16* __restrict__ Ahi, const bf16* __restrict__ Alo,
          const bf16* __restrict__ Whi, const bf16* __restrict__ Wlo,
          const float* __restrict__ bias, const float* __restrict__ resf,
          const bf16* __restrict__ reshi, const bf16* __restrict__ reslo,
          float* __restrict__ Cf, bf16* __restrict__ Chi, bf16* __restrict__ Clo,
          float* __restrict__ stats, int M, int Ncols, int K)
{
    extern __shared__ __align__(16) uint8_t sm[];
    GemmCoreB g;
    g.init(sm, blockIdx.y, blockIdx.x);
    g.run(Ahi, Alo, Whi, Wlo, M, Ncols, K);

    float ts0[4], ts1[4], tq0[4], tq1[4];
    if (STATS) {
#pragma unroll
        for (int nt = 0; nt < 4; nt++) { ts0[nt] = ts1[nt] = tq0[nt] = tq1[nt] = 0.f; }
    }

    const int qr = g.lid >> 2, qc = (g.lid & 3) * 2;
#pragma unroll
    for (int mt = 0; mt < 4; mt++) {
#pragma unroll
        for (int nt = 0; nt < 4; nt++) {
            int col = g.n0 + g.wn * 32 + nt * 8 + qc;
            float b0 = bias[col], b1 = bias[col + 1];
#pragma unroll
            for (int half = 0; half < 2; half++) {
                int row = g.m0 + g.wm * 64 + mt * 16 + qr + half * 8;
                if (row >= M) continue;
                float o0 = g.acc[mt][nt][half * 2 + 0] + b0;
                float o1 = g.acc[mt][nt][half * 2 + 1] + b1;
                size_t off = (size_t)row * Ncols + col;
                if (RESMODE == 1) {
                    float2 rr = *(const float2*)(resf + off);
                    o0 += rr.x; o1 += rr.y;
                } else if (RESMODE == 2) {
                    float2 rh = up2(*(const uint32_t*)(reshi + off));
                    float2 rl = up2(*(const uint32_t*)(reslo + off));
                    o0 += rh.x + rl.x; o1 += rh.y + rl.y;
                }
                if (RELU) { o0 = fmaxf(o0, 0.f); o1 = fmaxf(o1, 0.f); }
                if (STATS) {
                    ts0[nt] += o0; ts1[nt] += o1;
                    tq0[nt] = fmaf(o0, o0, tq0[nt]); tq1[nt] = fmaf(o1, o1, tq1[nt]);
                }
                if (OUTMODE == 0) {
                    *(float2*)(Cf + off) = make_float2(o0, o1);
                } else {
                    uint32_t lw, hw = packsplit(o0, o1, lw);
                    *(uint32_t*)(Chi + off) = hw;
                    *(uint32_t*)(Clo + off) = lw;
                }
            }
        }
    }
    if (STATS) {
#pragma unroll
        for (int nt = 0; nt < 4; nt++) {
            float a = ts0[nt], b = ts1[nt], c = tq0[nt], d = tq1[nt];
#pragma unroll
            for (int m = 4; m <= 16; m <<= 1) {
                a += __shfl_xor_sync(0xffffffff, a, m);
                b += __shfl_xor_sync(0xffffffff, b, m);
                c += __shfl_xor_sync(0xffffffff, c, m);
                d += __shfl_xor_sync(0xffffffff, d, m);
            }
            if (qr == 0) {
                int col = g.n0 + g.wn * 32 + nt * 8 + qc;
                redf(stats + col, a);
                redf(stats + col + 1, b);
                redf(stats + DIM + col, c);
                redf(stats + DIM + col + 1, d);
            }
        }
    }
}

// ---------------- fused QKV (fp32 A; blockIdx.x selects weight) -------------
__global__ void __launch_bounds__(256, 2)
qkv_gemm(const float* __restrict__ x,
         const bf16* __restrict__ qh, const bf16* __restrict__ ql,
         const bf16* __restrict__ kh, const bf16* __restrict__ kl,
         const bf16* __restrict__ vh, const bf16* __restrict__ vl,
         const float* __restrict__ bq, const float* __restrict__ bk,
         const float* __restrict__ bv,
         float* __restrict__ Qo, float* __restrict__ Ko, float* __restrict__ Vo)
{
    extern __shared__ __align__(16) uint8_t sm[];
    const bf16* Whi = qh; const bf16* Wlo = ql;
    const float* bias = bq; float* C = Qo;
    if (blockIdx.x == 1) { Whi = kh; Wlo = kl; bias = bk; C = Ko; }
    else if (blockIdx.x == 2) { Whi = vh; Wlo = vl; bias = bv; C = Vo; }

    GemmCoreF g;
    g.init(sm, blockIdx.y, 0);
    g.run(sm, x, Whi, Wlo, NN, 128, 128);

    const int qr = g.lid >> 2, qc = (g.lid & 3) * 2;
#pragma unroll
    for (int mt = 0; mt < 4; mt++) {
#pragma unroll
        for (int nt = 0; nt < 4; nt++) {
            int col = g.wn * 32 + nt * 8 + qc;
            float b0 = bias[col], b1 = bias[col + 1];
#pragma unroll
            for (int half = 0; half < 2; half++) {
                int row = g.m0 + g.wm * 64 + mt * 16 + qr + half * 8;
                if (row >= NN) continue;
                *(float2*)(C + (size_t)row * 128 + col) =
                    make_float2(g.acc[mt][nt][half * 2 + 0] + b0,
                                g.acc[mt][nt][half * 2 + 1] + b1);
            }
        }
    }
}

// ---------------- fused Ee GEMM (fp32 A) + edge score/logit/exp -------------
// grid (2, gE): blockIdx.x = head-half (n-tile), blockIdx.y = edge tile.
// logits clamped to [-5,5] BEFORE segment-max in reference => max-free softmax
// is exact; lg stores ex = exp(logit) directly.
union U16 { float4 q[4]; float f[16]; };

__global__ void __launch_bounds__(256, 2)
edge_gemm_fused(const float* __restrict__ ea,
                const bf16* __restrict__ weh, const bf16* __restrict__ wel,
                const float* __restrict__ bias,
                const int* __restrict__ ei, const float* __restrict__ Aw,
                const float* __restrict__ Qh, const float* __restrict__ Kh,
                bf16* __restrict__ ethi, bf16* __restrict__ etlo,
                float* __restrict__ lg)
{
    extern __shared__ __align__(16) uint8_t sm[];
    __shared__ float sAw[DIM];
    if (threadIdx.x < DIM) sAw[threadIdx.x] = Aw[threadIdx.x];

    GemmCoreF g;
    g.init(sm, blockIdx.y, blockIdx.x);
    g.run(sm, ea, weh, wel, NE, 256, 128);

    __syncthreads();   // tiles dead; reuse smem for the output tile
    float* sC = (float*)sm;          // 128 rows x 132 pitch (fits in 112640)
    const int qr = g.lid >> 2, qc = (g.lid & 3) * 2;
#pragma unroll
    for (int mt = 0; mt < 4; mt++) {
#pragma unroll
        for (int nt = 0; nt < 4; nt++) {
            int col = g.wn * 32 + nt * 8 + qc;
            float b0 = bias[g.n0 + col], b1 = bias[g.n0 + col + 1];
#pragma unroll
            for (int half = 0; half < 2; half++) {
                int row = g.wm * 64 + mt * 16 + qr + half * 8;
                *(float2*)(sC + row * 132 + col) =
                    make_float2(g.acc[mt][nt][half * 2 + 0] + b0,
                                g.acc[mt][nt][half * 2 + 1] + b1);
            }
        }
    }
    __syncthreads();

    const int e = threadIdx.x & 127;
    const int ge = g.m0 + e;                    // NE % 128 == 0
    const int src = ei[ge], dst = ei[NE + ge];
    (void)dst;
#pragma unroll
    for (int u = 0; u < 2; u++) {
        const int hl = (threadIdx.x >> 7) * 2 + u;
        const int h = blockIdx.x * 4 + hl;
        const float* ew = sC + e * 132 + hl * 32;
        U16 K4, Q4, EW, EB, ET;
        const float4* kp = (const float4*)(Kh + (size_t)src * DIM + h * DH);
        const float4* qp = (const float4*)(Qh + (size_t)ei[NE + ge] * DIM + h * DH);
#pragma unroll
        for (int q = 0; q < 4; q++) {
            K4.q[q] = kp[q]; Q4.q[q] = qp[q];
            EW.q[q] = *(const float4*)(ew + q * 4);
            EB.q[q] = *(const float4*)(ew + 16 + q * 4);
        }
        float logit = 0.f;
#pragma unroll
        for (int d = 0; d < 16; d++) {
            float s = (K4.f[d] + Q4.f[d]) * EW.f[d];
            float a = fabsf(s);
            float r = (a > 0.f) ? copysignf(sqrtf(a), s) : 0.f;
            float v = fmaxf(r + EB.f[d], 0.f);
            ET.f[d] = v;
            logit = fmaf(v, sAw[d * NH + h], logit);
        }
        logit = fminf(fmaxf(logit, -5.f), 5.f);
        uint32_t hw[8], lw[8];
#pragma unroll
        for (int q = 0; q < 8; q++) hw[q] = packsplit(ET.f[2 * q], ET.f[2 * q + 1], lw[q]);
        bf16* ph = ethi + (size_t)ge * DIM + h * DH;
        bf16* pl = etlo + (size_t)ge * DIM + h * DH;
        *(uint4*)ph       = make_uint4(hw[0], hw[1], hw[2], hw[3]);
        *((uint4*)ph + 1) = make_uint4(hw[4], hw[5], hw[6], hw[7]);
        *(uint4*)pl       = make_uint4(lw[0], lw[1], lw[2], lw[3]);
        *((uint4*)pl + 1) = make_uint4(lw[4], lw[5], lw[6], lw[7]);
        lg[ge * NH + h] = expf(logit);
    }
}

// ---------------- attention scatter (separate high-occupancy pass) ---------
__global__ void edge_scatter(const int* __restrict__ ei, const float* __restrict__ lg,
                             float* __restrict__ den, const float* __restrict__ Vh,
                             const bf16* __restrict__ ethi, const bf16* __restrict__ etlo,
                             float* __restrict__ wV, float* __restrict__ rowV)
{
    int t = blockIdx.x * blockDim.x + threadIdx.x;
    if (t >= NE * NH) return;
    int e = t >> 3, h = t & 7;
    int src = ei[e], dst = ei[NE + e];
    float ex = lg[t];
    redf(&den[dst * NH + h], ex);
    U16 V4, E4;
    const float4* vp = (const float4*)(Vh + (size_t)src * DIM + h * DH);
#pragma unroll
    for (int q = 0; q < 4; q++) V4.q[q] = vp[q];
    const uint4* ph = (const uint4*)(ethi + (size_t)e * DIM + h * DH);
    const uint4* pl = (const uint4*)(etlo + (size_t)e * DIM + h * DH);
#pragma unroll
    for (int half = 0; half < 2; half++) {
        uint4 H = ph[half], L = pl[half];
        uint32_t hw[4] = {H.x, H.y, H.z, H.w}, lw[4] = {L.x, L.y, L.z, L.w};
#pragma unroll
        for (int q = 0; q < 4; q++) {
            float2 fh = up2(hw[q]), fl = up2(lw[q]);
            E4.f[half * 8 + q * 2 + 0] = fh.x + fl.x;
            E4.f[half * 8 + q * 2 + 1] = fh.y + fl.y;
        }
    }
    float* wv = wV + (size_t)dst * DIM + h * DH;
    float* rv = rowV + (size_t)dst * DIM + h * DH;
#pragma unroll
    for (int q = 0; q < 4; q++) {
        red4(wv + q * 4, V4.q[q].x * ex, V4.q[q].y * ex, V4.q[q].z * ex, V4.q[q].w * ex);
        red4(rv + q * 4, E4.f[q * 4] * ex, E4.f[q * 4 + 1] * ex,
             E4.f[q * 4 + 2] * ex, E4.f[q * 4 + 3] * ex);
    }
}

// ---------------- misc / node / bn kernels ----------------
__global__ void preconv(const float* __restrict__ in, bf16* __restrict__ hi,
                        bf16* __restrict__ lo, long long n)
{
    long long i = ((long long)blockIdx.x * blockDim.x + threadIdx.x) * 4;
    if (i >= n) return;
    float4 v = *(const float4*)(in + i);
    uint2 h, l;
    split4(v, h, l);
    *(uint2*)(hi + i) = h;
    *(uint2*)(lo + i) = l;
}

__global__ void node_fix(const float* __restrict__ wV, const float* __restrict__ rowV,
                         const float* __restrict__ den,
                         const float* __restrict__ VeRow, const float* __restrict__ log_deg,
                         const float* __restrict__ deg_coef,
                         bf16* __restrict__ hatth, bf16* __restrict__ hattl)
{
    int t = blockIdx.x * blockDim.x + threadIdx.x;
    if (t >= NN * 64) return;
    int n = t >> 6, c0 = (t & 63) * 2, h = c0 >> 4, co = c0 & 15;
    size_t off = (size_t)n * DIM + c0;
    float inv = 1.f / (den[n * NH + h] + 1e-16f);
    float a0 = wV[off], a1 = wV[off + 1];
    const float* rv = rowV + (size_t)n * DIM + h * DH;
#pragma unroll
    for (int d2 = 0; d2 < 16; d2++) {
        float r = rv[d2];
        a0 = fmaf(r, VeRow[d2 * DIM + h * DH + co], a0);
        a1 = fmaf(r, VeRow[d2 * DIM + h * DH + co + 1], a1);
    }
    a0 *= inv; a1 *= inv;
    float ld = log_deg[n];
    float o0 = a0 * (deg_coef[2 * c0] + ld * deg_coef[2 * c0 + 1]);
    float o1 = a1 * (deg_coef[2 * c0 + 2] + ld * deg_coef[2 * c0 + 3]);
    uint32_t lw, hw = packsplit(o0, o1, lw);
    *(uint32_t*)(hatth + off) = hw;
    *(uint32_t*)(hattl + off) = lw;
}

template <bool PAIR>
__global__ void bn_apply(const float* __restrict__ v, float* __restrict__ outf,
                         bf16* __restrict__ outhi, bf16* __restrict__ outlo, int M,
                         const float* __restrict__ sums,
                         const float* __restrict__ g, const float* __restrict__ b, float invM)
{
    long long i = ((long long)blockIdx.x * blockDim.x + threadIdx.x) * 2;
    if (i >= (long long)M * DIM) return;
    int c = (int)(i & (DIM - 1));
    float m0 = sums[c] * invM, m1 = sums[c + 1] * invM;
    float var0 = fmaf(-m0, m0, sums[DIM + c] * invM);
    float var1 = fmaf(-m1, m1, sums[DIM + c + 1] * invM);
    float2 vv = *(const float2*)(v + i);
    float o0 = (vv.x - m0) * rsqrtf(var0 + 1e-5f) * g[c] + b[c];
    float o1 = (vv.y - m1) * rsqrtf(var1 + 1e-5f) * g[c + 1] + b[c + 1];
    if (!PAIR) {
        *(float2*)(outf + i) = make_float2(o0, o1);
    } else {
        uint32_t lw, hw = packsplit(o0, o1, lw);
        *(uint32_t*)(outhi + i) = hw;
        *(uint32_t*)(outlo + i) = lw;
    }
}

// ---------------- launch ----------------
#define SYM(var, sym) cudaGetSymbolAddress((void**)&var, sym)

extern "C" void kernel_launch(void* const* d_in, const int* in_sizes, int n_in,
                              void* d_out, int out_size)
{
    const float* x         = (const float*)d_in[0];
    const float* edge_attr = (const float*)d_in[1];
    const int*   ei        = (const int*)d_in[2];
    const float* log_deg   = (const float*)d_in[3];
    const float* Wq = (const float*)d_in[4],  *bq  = (const float*)d_in[5];
    const float* Wk = (const float*)d_in[6],  *bk  = (const float*)d_in[7];
    const float* We = (const float*)d_in[8],  *be  = (const float*)d_in[9];
    const float* Wv = (const float*)d_in[10], *bv  = (const float*)d_in[11];
    const float* Aw = (const float*)d_in[12], *VeRow = (const float*)d_in[13];
    const float* WOh = (const float*)d_in[14], *bOh = (const float*)d_in[15];
    const float* WOe = (const float*)d_in[16], *bOe = (const float*)d_in[17];
    const float* deg_coef = (const float*)d_in[18];
    const float* g1h = (const float*)d_in[19], *b1h = (const float*)d_in[20];
    const float* g1e = (const float*)d_in[21], *b1e = (const float*)d_in[22];
    const float* g2h = (const float*)d_in[23], *b2h = (const float*)d_in[24];
    const float* W1 = (const float*)d_in[25], *b1 = (const float*)d_in[26];
    const float* W2 = (const float*)d_in[27], *b2 = (const float*)d_in[28];

    float *Qh, *Kh, *Vh, *lg, *den, *wV, *rowV, *v1, *v2, *s1, *s2, *se;
    SYM(Qh, g_Qh); SYM(Kh, g_Kh); SYM(Vh, g_Vh);
    SYM(lg, g_lg); SYM(den, g_den);
    SYM(wV, g_wV); SYM(rowV, g_rowV);
    SYM(v1, g_v1); SYM(v2, g_v2);
    SYM(s1, g_s1); SYM(s2, g_s2); SYM(se, g_se);
    bf16 *ethi, *etlo, *hatth, *hattl, *hbnh, *hbnl, *h2ah, *h2al;
    SYM(ethi, g_ethi); SYM(etlo, g_etlo);
    SYM(hatth, g_hatth); SYM(hattl, g_hattl);
    SYM(hbnh, g_hbnh); SYM(hbnl, g_hbnl);
    SYM(h2ah, g_h2ah); SYM(h2al, g_h2al);
    bf16 *wq_h, *wq_l, *wk_h, *wk_l, *wv_h, *wv_l, *we_h, *we_l;
    bf16 *woh_h, *woh_l, *woe_h, *woe_l, *w1_h, *w1_l, *w2_h, *w2_l;
    SYM(wq_h, g_wq_h); SYM(wq_l, g_wq_l); SYM(wk_h, g_wk_h); SYM(wk_l, g_wk_l);
    SYM(wv_h, g_wv_h); SYM(wv_l, g_wv_l); SYM(we_h, g_we_h); SYM(we_l, g_we_l);
    SYM(woh_h, g_woh_h); SYM(woh_l, g_woh_l); SYM(woe_h, g_woe_h); SYM(woe_l, g_woe_l);
    SYM(w1_h, g_w1_h); SYM(w1_l, g_w1_l); SYM(w2_h, g_w2_h); SYM(w2_l, g_w2_l);

    float* hout = (float*)d_out;
    float* eout = (float*)d_out + (size_t)NN * DIM;

    cudaFuncSetAttribute(mma_gemmB<1, 0, false, true >, cudaFuncAttributeMaxDynamicSharedMemorySize, SMB_TOTAL);
    cudaFuncSetAttribute(mma_gemmB<0, 1, true,  false>, cudaFuncAttributeMaxDynamicSharedMemorySize, SMB_TOTAL);
    cudaFuncSetAttribute(mma_gemmB<2, 0, false, true >, cudaFuncAttributeMaxDynamicSharedMemorySize, SMB_TOTAL);
    cudaFuncSetAttribute(qkv_gemm, cudaFuncAttributeMaxDynamicSharedMemorySize, SMF_TOTAL);
    cudaFuncSetAttribute(edge_gemm_fused, cudaFuncAttributeMaxDynamicSharedMemorySize, SMF_TOTAL);

    // ---- pre-convert weights only (small) ----
    auto pc = [&](const float* in, bf16* h, bf16* l, long long n) {
        preconv<<<cdiv(n / 4, 256), 256>>>(in, h, l, n);
    };
    pc(Wq, wq_h, wq_l, DIM * DIM);
    pc(Wk, wk_h, wk_l, DIM * DIM);
    pc(Wv, wv_h, wv_l, DIM * DIM);
    pc(We, we_h, we_l, DIM * 2 * DIM);
    pc(WOh, woh_h, woh_l, DIM * DIM);
    pc(WOe, woe_h, woe_l, DIM * DIM);
    pc(W1, w1_h, w1_l, DIM * 2 * DIM);
    pc(W2, w2_h, w2_l, 2 * DIM * DIM);

    // init accumulators
    cudaMemsetAsync(wV, 0, (size_t)NN * DIM * sizeof(float));
    cudaMemsetAsync(rowV, 0, (size_t)NN * DIM * sizeof(float));
    cudaMemsetAsync(den, 0, (size_t)NN * NH * sizeof(float));
    cudaMemsetAsync(s1, 0, 2 * DIM * sizeof(float));
    cudaMemsetAsync(s2, 0, 2 * DIM * sizeof(float));
    cudaMemsetAsync(se, 0, 2 * DIM * sizeof(float));

    const int gN = cdiv(NN, 128), gE = cdiv(NE, 128);

    // Q/K/V in one launch (fp32 x read directly; 3 siblings share it via L2)
    qkv_gemm<<<dim3(3, gN), 256, SMF_TOTAL>>>(x, wq_h, wq_l, wk_h, wk_l,
                                              wv_h, wv_l, bq, bk, bv, Qh, Kh, Vh);

    // fused Ee GEMM (fp32 edge_attr) + score/logit + exp (max-free softmax)
    edge_gemm_fused<<<dim3(2, gE), 256, SMF_TOTAL>>>(edge_attr, we_h, we_l, be,
                                                     ei, Aw, Qh, Kh, ethi, etlo, lg);

    // denominator + unnormalized scatter (high-occupancy separate pass)
    edge_scatter<<<cdiv(NE * NH, 256), 256>>>(ei, lg, den, Vh, ethi, etlo, wV, rowV);

    node_fix<<<cdiv(NN * 64, 256), 256>>>(wV, rowV, den, VeRow, log_deg, deg_coef, hatth, hattl);

    // h path: WOh + residual(x) -> v1 with fused stats; BN1 -> hbn pair
    mma_gemmB<1, 0, false, true><<<dim3(1, gN), 256, SMB_TOTAL>>>(
        hatth, hattl, woh_h, woh_l, bOh, x, nullptr, nullptr, v1, nullptr, nullptr, s1, NN, 128, 128);
    bn_apply<true><<<cdiv((long long)NN * 64, 256), 256>>>(v1, nullptr, hbnh, hbnl, NN, s1, g1h, b1h, 1.f / NN);

    // e path: WOe + residual(edge_attr) -> eout with fused stats; BN apply
    mma_gemmB<1, 0, false, true><<<dim3(1, gE), 256, SMB_TOTAL>>>(
        ethi, etlo, woe_h, woe_l, bOe, edge_attr, nullptr, nullptr, eout, nullptr, nullptr, se, NE, 128, 128);
    bn_apply<false><<<cdiv((long long)NE * 64, 256), 256>>>(eout, eout, nullptr, nullptr, NE, se, g1e, b1e, 1.f / NE);

    // FFN: W1(relu) -> h2a pair; W2 + residual(hbn pair) -> v2 with stats; BN2 -> hout
    mma_gemmB<0, 1, true, false><<<dim3(2, gN), 256, SMB_TOTAL>>>(
        hbnh, hbnl, w1_h, w1_l, b1, nullptr, nullptr, nullptr, nullptr, h2ah, h2al, nullptr, NN, 256, 128);
    mma_gemmB<2, 0, false, true><<<dim3(1, gN), 256, SMB_TOTAL>>>(
        h2ah, h2al, w2_h, w2_l, b2, nullptr, hbnh, hbnl, v2, nullptr, nullptr, s2, NN, 128, 256);
    bn_apply<false><<<cdiv((long long)NN * 64, 256), 256>>>(v2, hout, nullptr, nullptr, NN, s2, g2h, b2h, 1.f / NN);
}

// round 10
// speedup vs baseline: 1.0912x; 1.0912x over previous
#include <cuda_runtime.h>
#include <cuda_bf16.h>
#include <math.h>
#include <stdint.h>

#define NN 40000
#define NE 640000
#define DIM 128
#define NH 8
#define DH 16

typedef __nv_bfloat16 bf16;

// ---------------- scratch (device globals: allocation-free) ----------------
__device__ float g_Qh[(size_t)NN * DIM];
__device__ float g_Kh[(size_t)NN * DIM];
__device__ float g_Vh[(size_t)NN * DIM];
__device__ float g_lg[(size_t)NE * NH];
__device__ float g_den[(size_t)NN * NH];
__device__ float g_wV[(size_t)NN * DIM];
__device__ float g_rowV[(size_t)NN * DIM];
__device__ float g_v1[(size_t)NN * DIM];
__device__ float g_v2[(size_t)NN * DIM];
__device__ float g_s1[2 * DIM];
__device__ float g_s2[2 * DIM];
__device__ float g_se[2 * DIM];
// bf16 hi/lo pairs
__device__ bf16 g_xhi[(size_t)NN * DIM],  g_xlo[(size_t)NN * DIM];
__device__ bf16 g_eahi[(size_t)NE * DIM], g_ealo[(size_t)NE * DIM];
__device__ bf16 g_ethi[(size_t)NE * DIM], g_etlo[(size_t)NE * DIM];
__device__ bf16 g_hatth[(size_t)NN * DIM], g_hattl[(size_t)NN * DIM];
__device__ bf16 g_hbnh[(size_t)NN * DIM],  g_hbnl[(size_t)NN * DIM];
__device__ bf16 g_h2ah[(size_t)NN * 2 * DIM], g_h2al[(size_t)NN * 2 * DIM];
__device__ bf16 g_wq_h[DIM * DIM], g_wq_l[DIM * DIM];
__device__ bf16 g_wk_h[DIM * DIM], g_wk_l[DIM * DIM];
__device__ bf16 g_wv_h[DIM * DIM], g_wv_l[DIM * DIM];
__device__ bf16 g_we_h[DIM * 2 * DIM], g_we_l[DIM * 2 * DIM];
__device__ bf16 g_woh_h[DIM * DIM], g_woh_l[DIM * DIM];
__device__ bf16 g_woe_h[DIM * DIM], g_woe_l[DIM * DIM];
__device__ bf16 g_w1_h[DIM * 2 * DIM], g_w1_l[DIM * 2 * DIM];
__device__ bf16 g_w2_h[2 * DIM * DIM], g_w2_l[2 * DIM * DIM];

static inline int cdiv(long long a, long long b) { return (int)((a + b - 1) / b); }

// ---------------- helpers ----------------
__device__ __forceinline__ uint32_t smem_u32(const void* p) {
    uint32_t a;
    asm("{ .reg .u64 t; cvta.to.shared.u64 t, %1; cvt.u32.u64 %0, t; }" : "=r"(a) : "l"(p));
    return a;
}
__device__ __forceinline__ void ldsm4(uint32_t (&r)[4], uint32_t addr) {
    asm volatile("ldmatrix.sync.aligned.m8n8.x4.shared.b16 {%0,%1,%2,%3}, [%4];"
                 : "=r"(r[0]), "=r"(r[1]), "=r"(r[2]), "=r"(r[3]) : "r"(addr));
}
__device__ __forceinline__ void ldsm4t(uint32_t (&r)[4], uint32_t addr) {
    asm volatile("ldmatrix.sync.aligned.m8n8.x4.trans.shared.b16 {%0,%1,%2,%3}, [%4];"
                 : "=r"(r[0]), "=r"(r[1]), "=r"(r[2]), "=r"(r[3]) : "r"(addr));
}
__device__ __forceinline__ void mma16816(float (&d)[4], const uint32_t (&a)[4], const uint32_t* b) {
    asm volatile("mma.sync.aligned.m16n8k16.row.col.f32.bf16.bf16.f32 "
                 "{%0,%1,%2,%3}, {%4,%5,%6,%7}, {%8,%9}, {%0,%1,%2,%3};"
                 : "+f"(d[0]), "+f"(d[1]), "+f"(d[2]), "+f"(d[3])
                 : "r"(a[0]), "r"(a[1]), "r"(a[2]), "r"(a[3]), "r"(b[0]), "r"(b[1]));
}
__device__ __forceinline__ uint32_t pack2(bf16 a, bf16 b) {
    return (uint32_t)__bfloat16_as_ushort(a) | ((uint32_t)__bfloat16_as_ushort(b) << 16);
}
__device__ __forceinline__ float2 up2(uint32_t u) {
    return make_float2(__bfloat162float(__ushort_as_bfloat16((unsigned short)(u & 0xffff))),
                       __bfloat162float(__ushort_as_bfloat16((unsigned short)(u >> 16))));
}
__device__ __forceinline__ void split4(float4 v, uint2& hi, uint2& lo) {
    bf16 hx = __float2bfloat16(v.x), hy = __float2bfloat16(v.y);
    bf16 hz = __float2bfloat16(v.z), hw = __float2bfloat16(v.w);
    hi = make_uint2(pack2(hx, hy), pack2(hz, hw));
    lo = make_uint2(pack2(__float2bfloat16(v.x - __bfloat162float(hx)),
                          __float2bfloat16(v.y - __bfloat162float(hy))),
                    pack2(__float2bfloat16(v.z - __bfloat162float(hz)),
                          __float2bfloat16(v.w - __bfloat162float(hw))));
}
__device__ __forceinline__ uint32_t packsplit(float a, float b, uint32_t& lo) {
    bf16 h0 = __float2bfloat16(a), h1 = __float2bfloat16(b);
    lo = pack2(__float2bfloat16(a - __bfloat162float(h0)),
               __float2bfloat16(b - __bfloat162float(h1)));
    return pack2(h0, h1);
}
__device__ __forceinline__ void cp16(uint32_t dst, const void* src, int sz) {
    asm volatile("cp.async.cg.shared.global [%0], [%1], 16, %2;" :: "r"(dst), "l"(src), "r"(sz));
}
#define CP_COMMIT() asm volatile("cp.async.commit_group;" ::: "memory")
#define CP_WAIT0()  asm volatile("cp.async.wait_group 0;" ::: "memory")
#define CP_WAIT1()  asm volatile("cp.async.wait_group 1;" ::: "memory")

__device__ __forceinline__ void red4(float* p, float a, float b, float c, float d) {
    asm volatile("red.global.add.v4.f32 [%0], {%1,%2,%3,%4};"
                 :: "l"(p), "f"(a), "f"(b), "f"(c), "f"(d) : "memory");
}
__device__ __forceinline__ void redf(float* p, float a) {
    asm volatile("red.global.add.f32 [%0], %1;" :: "l"(p), "f"(a) : "memory");
}

// ---------------- bf16-pair GEMM core: 128x128 tile, 256 thr, 2-stage pipe ----
#define STG    37888u
#define AHI_O  0u
#define ALO_O  10240u
#define BHI_O  20480u
#define BLO_O  29184u
#define SMB_TOTAL 75776

struct GemmCoreB {
    uint32_t sb;
    int tid, lid, wm, wn, m0, n0;
    float acc[4][4][4];

    __device__ __forceinline__ void init(uint8_t* smp, int bm, int bn) {
        sb = smem_u32(smp);
        tid = threadIdx.x; lid = tid & 31;
        int wid = tid >> 5;
        wm = wid >> 2; wn = wid & 3;
        m0 = bm * 128; n0 = bn * 128;
#pragma unroll
        for (int i = 0; i < 4; i++)
#pragma unroll
            for (int j = 0; j < 4; j++)
#pragma unroll
                for (int q = 0; q < 4; q++) acc[i][j][q] = 0.f;
    }
    __device__ __forceinline__ void stage(int buf, const bf16* Ahi, const bf16* Alo,
                                          const bf16* Whi, const bf16* Wlo,
                                          int M, int Ncols, int K, int kb) {
        uint32_t base = sb + (uint32_t)buf * STG;
#pragma unroll
        for (int i = 0; i < 2; i++) {
            int c = tid + i * 256;
            int row = c >> 2, gr = c & 3;
            bool ok = (m0 + row) < M;
            size_t go = (size_t)(ok ? m0 + row : 0) * K + kb + gr * 8;
            uint32_t d = base + (uint32_t)row * 80 + (uint32_t)gr * 16;
            cp16(d + AHI_O, Ahi + go, ok ? 16 : 0);
            cp16(d + ALO_O, Alo + go, ok ? 16 : 0);
        }
#pragma unroll
        for (int i = 0; i < 2; i++) {
            int c = tid + i * 256;
            int k = c >> 4, gr = c & 15;
            size_t go = (size_t)(kb + k) * Ncols + n0 + gr * 8;
            uint32_t d = base + (uint32_t)k * 272 + (uint32_t)gr * 16;
            cp16(d + BHI_O, Whi + go, 16);
            cp16(d + BLO_O, Wlo + go, 16);
        }
        CP_COMMIT();
    }
    __device__ __forceinline__ void compute(int buf) {
        uint32_t base = sb + (uint32_t)buf * STG;
#pragma unroll
        for (int ks = 0; ks < 32; ks += 16) {
            uint32_t bhi[4][2], blo[4][2];
            const uint32_t brow = (uint32_t)(ks + (lid & 15)) * 272 + (uint32_t)((lid >> 4) * 16);
#pragma unroll
            for (int p = 0; p < 2; p++) {
                uint32_t baddr = base + brow + (uint32_t)(wn * 32 + p * 16) * 2;
                uint32_t r[4];
                ldsm4t(r, baddr + BHI_O);
                bhi[2 * p][0] = r[0]; bhi[2 * p][1] = r[1];
                bhi[2 * p + 1][0] = r[2]; bhi[2 * p + 1][1] = r[3];
                ldsm4t(r, baddr + BLO_O);
                blo[2 * p][0] = r[0]; blo[2 * p][1] = r[1];
                blo[2 * p + 1][0] = r[2]; blo[2 * p + 1][1] = r[3];
            }
            const uint32_t arow = (uint32_t)(wm * 64 + (lid & 15)) * 80
                                + (uint32_t)ks * 2 + (uint32_t)(lid >> 4) * 16;
#pragma unroll
            for (int mt = 0; mt < 4; mt++) {
                uint32_t aaddr = base + arow + (uint32_t)mt * (16 * 80);
                uint32_t ahi4[4], alo4[4];
                ldsm4(ahi4, aaddr + AHI_O);
                ldsm4(alo4, aaddr + ALO_O);
#pragma unroll
                for (int nt = 0; nt < 4; nt++) {
                    mma16816(acc[mt][nt], ahi4, bhi[nt]);
                    mma16816(acc[mt][nt], ahi4, blo[nt]);
                    mma16816(acc[mt][nt], alo4, bhi[nt]);
                }
            }
        }
    }
    __device__ __forceinline__ void run(const bf16* Ahi, const bf16* Alo,
                                        const bf16* Whi, const bf16* Wlo,
                                        int M, int Ncols, int K) {
        const int nch = K >> 5;
        stage(0, Ahi, Alo, Whi, Wlo, M, Ncols, K, 0);
        if (nch > 1) stage(1, Ahi, Alo, Whi, Wlo, M, Ncols, K, 32);
        for (int i = 0; i < nch; i++) {
            if (i == nch - 1) { CP_WAIT0(); } else { CP_WAIT1(); }
            __syncthreads();
            compute(i & 1);
            if (i + 2 < nch) {
                __syncthreads();
                stage(i & 1, Ahi, Alo, Whi, Wlo, M, Ncols, K, (i + 2) * 32);
            }
        }
    }
};

// ---------------- generic GEMM (m-tile = blockIdx.y, n-tile = blockIdx.x) ----
// RESMODE 0=none 1=f32 2=bf16pair; OUTMODE 0=f32 1=pair; STATS: fused col sums
template <int RESMODE, int OUTMODE, bool RELU, bool STATS>
__global__ void __launch_bounds__(256, 2)
mma_gemmB(const bf16* __restrict__ Ahi, const bf16* __restrict__ Alo,
          const bf16* __restrict__ Whi, const bf16* __restrict__ Wlo,
          const float* __restrict__ bias, const float* __restrict__ resf,
          const bf16* __restrict__ reshi, const bf16* __restrict__ reslo,
          float* __restrict__ Cf, bf16* __restrict__ Chi, bf16* __restrict__ Clo,
          float* __restrict__ stats, int M, int Ncols, int K)
{
    extern __shared__ __align__(16) uint8_t sm[];
    GemmCoreB g;
    g.init(sm, blockIdx.y, blockIdx.x);
    g.run(Ahi, Alo, Whi, Wlo, M, Ncols, K);

    float ts0[4], ts1[4], tq0[4], tq1[4];
    if (STATS) {
#pragma unroll
        for (int nt = 0; nt < 4; nt++) { ts0[nt] = ts1[nt] = tq0[nt] = tq1[nt] = 0.f; }
    }

    const int qr = g.lid >> 2, qc = (g.lid & 3) * 2;
#pragma unroll
    for (int mt = 0; mt < 4; mt++) {
#pragma unroll
        for (int nt = 0; nt < 4; nt++) {
            int col = g.n0 + g.wn * 32 + nt * 8 + qc;
            float b0 = bias[col], b1 = bias[col + 1];
#pragma unroll
            for (int half = 0; half < 2; half++) {
                int row = g.m0 + g.wm * 64 + mt * 16 + qr + half * 8;
                if (row >= M) continue;
                float o0 = g.acc[mt][nt][half * 2 + 0] + b0;
                float o1 = g.acc[mt][nt][half * 2 + 1] + b1;
                size_t off = (size_t)row * Ncols + col;
                if (RESMODE == 1) {
                    float2 rr = *(const float2*)(resf + off);
                    o0 += rr.x; o1 += rr.y;
                } else if (RESMODE == 2) {
                    float2 rh = up2(*(const uint32_t*)(reshi + off));
                    float2 rl = up2(*(const uint32_t*)(reslo + off));
                    o0 += rh.x + rl.x; o1 += rh.y + rl.y;
                }
                if (RELU) { o0 = fmaxf(o0, 0.f); o1 = fmaxf(o1, 0.f); }
                if (STATS) {
                    ts0[nt] += o0; ts1[nt] += o1;
                    tq0[nt] = fmaf(o0, o0, tq0[nt]); tq1[nt] = fmaf(o1, o1, tq1[nt]);
                }
                if (OUTMODE == 0) {
                    *(float2*)(Cf + off) = make_float2(o0, o1);
                } else {
                    uint32_t lw, hw = packsplit(o0, o1, lw);
                    *(uint32_t*)(Chi + off) = hw;
                    *(uint32_t*)(Clo + off) = lw;
                }
            }
        }
    }
    if (STATS) {
#pragma unroll
        for (int nt = 0; nt < 4; nt++) {
            float a = ts0[nt], b = ts1[nt], c = tq0[nt], d = tq1[nt];
#pragma unroll
            for (int m = 4; m <= 16; m <<= 1) {
                a += __shfl_xor_sync(0xffffffff, a, m);
                b += __shfl_xor_sync(0xffffffff, b, m);
                c += __shfl_xor_sync(0xffffffff, c, m);
                d += __shfl_xor_sync(0xffffffff, d, m);
            }
            if (qr == 0) {
                int col = g.n0 + g.wn * 32 + nt * 8 + qc;
                redf(stats + col, a);
                redf(stats + col + 1, b);
                redf(stats + DIM + col, c);
                redf(stats + DIM + col + 1, d);
            }
        }
    }
}

// ---------------- fused QKV (blockIdx.x selects weight, y = m tile) ----------
__global__ void __launch_bounds__(256, 2)
qkv_gemm(const bf16* __restrict__ xhi, const bf16* __restrict__ xlo,
         const bf16* __restrict__ qh, const bf16* __restrict__ ql,
         const bf16* __restrict__ kh, const bf16* __restrict__ kl,
         const bf16* __restrict__ vh, const bf16* __restrict__ vl,
         const float* __restrict__ bq, const float* __restrict__ bk,
         const float* __restrict__ bv,
         float* __restrict__ Qo, float* __restrict__ Ko, float* __restrict__ Vo)
{
    extern __shared__ __align__(16) uint8_t sm[];
    const bf16* Whi = qh; const bf16* Wlo = ql;
    const float* bias = bq; float* C = Qo;
    if (blockIdx.x == 1) { Whi = kh; Wlo = kl; bias = bk; C = Ko; }
    else if (blockIdx.x == 2) { Whi = vh; Wlo = vl; bias = bv; C = Vo; }

    GemmCoreB g;
    g.init(sm, blockIdx.y, 0);
    g.run(xhi, xlo, Whi, Wlo, NN, 128, 128);

    const int qr = g.lid >> 2, qc = (g.lid & 3) * 2;
#pragma unroll
    for (int mt = 0; mt < 4; mt++) {
#pragma unroll
        for (int nt = 0; nt < 4; nt++) {
            int col = g.wn * 32 + nt * 8 + qc;
            float b0 = bias[col], b1 = bias[col + 1];
#pragma unroll
            for (int half = 0; half < 2; half++) {
                int row = g.m0 + g.wm * 64 + mt * 16 + qr + half * 8;
                if (row >= NN) continue;
                *(float2*)(C + (size_t)row * 128 + col) =
                    make_float2(g.acc[mt][nt][half * 2 + 0] + b0,
                                g.acc[mt][nt][half * 2 + 1] + b1);
            }
        }
    }
}

// ---------------- fused Ee GEMM + edge score/logit/exp ----------------
// grid (2, gE): blockIdx.x = head-half (n-tile), blockIdx.y = edge tile.
// logits are clamped to [-5,5] BEFORE segment-max in the reference, so
// max-free softmax is exact; lg stores ex = exp(logit).
union U16 { float4 q[4]; float f[16]; };

__global__ void __launch_bounds__(256, 2)
edge_gemm_fused(const bf16* __restrict__ eahi, const bf16* __restrict__ ealo,
                const bf16* __restrict__ weh, const bf16* __restrict__ wel,
                const float* __restrict__ bias,
                const int* __restrict__ ei, const float* __restrict__ Aw,
                const float* __restrict__ Qh, const float* __restrict__ Kh,
                bf16* __restrict__ ethi, bf16* __restrict__ etlo,
                float* __restrict__ lg)
{
    extern __shared__ __align__(16) uint8_t sm[];
    __shared__ float sAw[DIM];
    if (threadIdx.x < DIM) sAw[threadIdx.x] = Aw[threadIdx.x];

    GemmCoreB g;
    g.init(sm, blockIdx.y, blockIdx.x);
    g.run(eahi, ealo, weh, wel, NE, 256, 128);

    __syncthreads();   // tiles dead; reuse smem for the output tile
    float* sC = (float*)sm;          // 128 rows x 132 pitch
    const int qr = g.lid >> 2, qc = (g.lid & 3) * 2;
#pragma unroll
    for (int mt = 0; mt < 4; mt++) {
#pragma unroll
        for (int nt = 0; nt < 4; nt++) {
            int col = g.wn * 32 + nt * 8 + qc;
            float b0 = bias[g.n0 + col], b1 = bias[g.n0 + col + 1];
#pragma unroll
            for (int half = 0; half < 2; half++) {
                int row = g.wm * 64 + mt * 16 + qr + half * 8;
                *(float2*)(sC + row * 132 + col) =
                    make_float2(g.acc[mt][nt][half * 2 + 0] + b0,
                                g.acc[mt][nt][half * 2 + 1] + b1);
            }
        }
    }
    __syncthreads();

    const int e = threadIdx.x & 127;
    const int ge = g.m0 + e;                    // NE % 128 == 0
    const int src = ei[ge], dst = ei[NE + ge];
    (void)dst;
#pragma unroll
    for (int u = 0; u < 2; u++) {
        const int hl = (threadIdx.x >> 7) * 2 + u;
        const int h = blockIdx.x * 4 + hl;
        const float* ew = sC + e * 132 + hl * 32;
        U16 K4, Q4, EW, EB, ET;
        const float4* kp = (const float4*)(Kh + (size_t)src * DIM + h * DH);
        const float4* qp = (const float4*)(Qh + (size_t)dst * DIM + h * DH);
#pragma unroll
        for (int q = 0; q < 4; q++) {
            K4.q[q] = kp[q]; Q4.q[q] = qp[q];
            EW.q[q] = *(const float4*)(ew + q * 4);
            EB.q[q] = *(const float4*)(ew + 16 + q * 4);
        }
        float logit = 0.f;
#pragma unroll
        for (int d = 0; d < 16; d++) {
            float s = (K4.f[d] + Q4.f[d]) * EW.f[d];
            float a = fabsf(s);
            float r = (a > 0.f) ? copysignf(sqrtf(a), s) : 0.f;
            float v = fmaxf(r + EB.f[d], 0.f);
            ET.f[d] = v;
            logit = fmaf(v, sAw[d * NH + h], logit);
        }
        logit = fminf(fmaxf(logit, -5.f), 5.f);
        // write et as bf16 hi/lo
        uint32_t hw[8], lw[8];
#pragma unroll
        for (int q = 0; q < 8; q++) hw[q] = packsplit(ET.f[2 * q], ET.f[2 * q + 1], lw[q]);
        bf16* ph = ethi + (size_t)ge * DIM + h * DH;
        bf16* pl = etlo + (size_t)ge * DIM + h * DH;
        *(uint4*)ph       = make_uint4(hw[0], hw[1], hw[2], hw[3]);
        *((uint4*)ph + 1) = make_uint4(hw[4], hw[5], hw[6], hw[7]);
        *(uint4*)pl       = make_uint4(lw[0], lw[1], lw[2], lw[3]);
        *((uint4*)pl + 1) = make_uint4(lw[4], lw[5], lw[6], lw[7]);
        lg[ge * NH + h] = expf(logit);
    }
}

// ---------------- misc / edge / node / bn kernels ----------------
__global__ void preconv(const float* __restrict__ in, bf16* __restrict__ hi,
                        bf16* __restrict__ lo, long long n)
{
    long long i = ((long long)blockIdx.x * blockDim.x + threadIdx.x) * 4;
    if (i >= n) return;
    float4 v = *(const float4*)(in + i);
    uint2 h, l;
    split4(v, h, l);
    *(uint2*)(hi + i) = h;
    *(uint2*)(lo + i) = l;
}

// denominator + unnormalized scatter (normalize in node_fix); lg holds ex.
__global__ void edge_scatter(const int* __restrict__ ei, const float* __restrict__ lg,
                             float* __restrict__ den, const float* __restrict__ Vh,
                             const bf16* __restrict__ ethi, const bf16* __restrict__ etlo,
                             float* __restrict__ wV, float* __restrict__ rowV)
{
    int t = blockIdx.x * blockDim.x + threadIdx.x;
    if (t >= NE * NH) return;
    int e = t >> 3, h = t & 7;
    int src = ei[e], dst = ei[NE + e];
    float ex = lg[t];
    redf(&den[dst * NH + h], ex);
    U16 V4, E4;
    const float4* vp = (const float4*)(Vh + (size_t)src * DIM + h * DH);
#pragma unroll
    for (int q = 0; q < 4; q++) V4.q[q] = vp[q];
    const uint4* ph = (const uint4*)(ethi + (size_t)e * DIM + h * DH);
    const uint4* pl = (const uint4*)(etlo + (size_t)e * DIM + h * DH);
#pragma unroll
    for (int half = 0; half < 2; half++) {
        uint4 H = ph[half], L = pl[half];
        uint32_t hw[4] = {H.x, H.y, H.z, H.w}, lw[4] = {L.x, L.y, L.z, L.w};
#pragma unroll
        for (int q = 0; q < 4; q++) {
            float2 fh = up2(hw[q]), fl = up2(lw[q]);
            E4.f[half * 8 + q * 2 + 0] = fh.x + fl.x;
            E4.f[half * 8 + q * 2 + 1] = fh.y + fl.y;
        }
    }
    float* wv = wV + (size_t)dst * DIM + h * DH;
    float* rv = rowV + (size_t)dst * DIM + h * DH;
#pragma unroll
    for (int q = 0; q < 4; q++) {
        red4(wv + q * 4, V4.q[q].x * ex, V4.q[q].y * ex, V4.q[q].z * ex, V4.q[q].w * ex);
        red4(rv + q * 4, E4.f[q * 4] * ex, E4.f[q * 4 + 1] * ex,
             E4.f[q * 4 + 2] * ex, E4.f[q * 4 + 3] * ex);
    }
}

__global__ void node_fix(const float* __restrict__ wV, const float* __restrict__ rowV,
                         const float* __restrict__ den,
                         const float* __restrict__ VeRow, const float* __restrict__ log_deg,
                         const float* __restrict__ deg_coef,
                         bf16* __restrict__ hatth, bf16* __restrict__ hattl)
{
    int t = blockIdx.x * blockDim.x + threadIdx.x;
    if (t >= NN * 64) return;
    int n = t >> 6, c0 = (t & 63) * 2, h = c0 >> 4, co = c0 & 15;
    size_t off = (size_t)n * DIM + c0;
    float inv = 1.f / (den[n * NH + h] + 1e-16f);
    float a0 = wV[off], a1 = wV[off + 1];
    const float* rv = rowV + (size_t)n * DIM + h * DH;
#pragma unroll
    for (int d2 = 0; d2 < 16; d2++) {
        float r = rv[d2];
        a0 = fmaf(r, VeRow[d2 * DIM + h * DH + co], a0);
        a1 = fmaf(r, VeRow[d2 * DIM + h * DH + co + 1], a1);
    }
    a0 *= inv; a1 *= inv;
    float ld = log_deg[n];
    float o0 = a0 * (deg_coef[2 * c0] + ld * deg_coef[2 * c0 + 1]);
    float o1 = a1 * (deg_coef[2 * c0 + 2] + ld * deg_coef[2 * c0 + 3]);
    uint32_t lw, hw = packsplit(o0, o1, lw);
    *(uint32_t*)(hatth + off) = hw;
    *(uint32_t*)(hattl + off) = lw;
}

template <bool PAIR>
__global__ void bn_apply(const float* __restrict__ v, float* __restrict__ outf,
                         bf16* __restrict__ outhi, bf16* __restrict__ outlo, int M,
                         const float* __restrict__ sums,
                         const float* __restrict__ g, const float* __restrict__ b, float invM)
{
    long long i = ((long long)blockIdx.x * blockDim.x + threadIdx.x) * 2;
    if (i >= (long long)M * DIM) return;
    int c = (int)(i & (DIM - 1));
    float m0 = sums[c] * invM, m1 = sums[c + 1] * invM;
    float var0 = fmaf(-m0, m0, sums[DIM + c] * invM);
    float var1 = fmaf(-m1, m1, sums[DIM + c + 1] * invM);
    float2 vv = *(const float2*)(v + i);
    float o0 = (vv.x - m0) * rsqrtf(var0 + 1e-5f) * g[c] + b[c];
    float o1 = (vv.y - m1) * rsqrtf(var1 + 1e-5f) * g[c + 1] + b[c + 1];
    if (!PAIR) {
        *(float2*)(outf + i) = make_float2(o0, o1);
    } else {
        uint32_t lw, hw = packsplit(o0, o1, lw);
        *(uint32_t*)(outhi + i) = hw;
        *(uint32_t*)(outlo + i) = lw;
    }
}

// ---------------- launch ----------------
#define SYM(var, sym) cudaGetSymbolAddress((void**)&var, sym)

extern "C" void kernel_launch(void* const* d_in, const int* in_sizes, int n_in,
                              void* d_out, int out_size)
{
    const float* x         = (const float*)d_in[0];
    const float* edge_attr = (const float*)d_in[1];
    const int*   ei        = (const int*)d_in[2];
    const float* log_deg   = (const float*)d_in[3];
    const float* Wq = (const float*)d_in[4],  *bq  = (const float*)d_in[5];
    const float* Wk = (const float*)d_in[6],  *bk  = (const float*)d_in[7];
    const float* We = (const float*)d_in[8],  *be  = (const float*)d_in[9];
    const float* Wv = (const float*)d_in[10], *bv  = (const float*)d_in[11];
    const float* Aw = (const float*)d_in[12], *VeRow = (const float*)d_in[13];
    const float* WOh = (const float*)d_in[14], *bOh = (const float*)d_in[15];
    const float* WOe = (const float*)d_in[16], *bOe = (const float*)d_in[17];
    const float* deg_coef = (const float*)d_in[18];
    const float* g1h = (const float*)d_in[19], *b1h = (const float*)d_in[20];
    const float* g1e = (const float*)d_in[21], *b1e = (const float*)d_in[22];
    const float* g2h = (const float*)d_in[23], *b2h = (const float*)d_in[24];
    const float* W1 = (const float*)d_in[25], *b1 = (const float*)d_in[26];
    const float* W2 = (const float*)d_in[27], *b2 = (const float*)d_in[28];

    float *Qh, *Kh, *Vh, *lg, *den, *wV, *rowV, *v1, *v2, *s1, *s2, *se;
    SYM(Qh, g_Qh); SYM(Kh, g_Kh); SYM(Vh, g_Vh);
    SYM(lg, g_lg); SYM(den, g_den);
    SYM(wV, g_wV); SYM(rowV, g_rowV);
    SYM(v1, g_v1); SYM(v2, g_v2);
    SYM(s1, g_s1); SYM(s2, g_s2); SYM(se, g_se);
    bf16 *xhi, *xlo, *eahi, *ealo, *ethi, *etlo, *hatth, *hattl, *hbnh, *hbnl, *h2ah, *h2al;
    SYM(xhi, g_xhi); SYM(xlo, g_xlo); SYM(eahi, g_eahi); SYM(ealo, g_ealo);
    SYM(ethi, g_ethi); SYM(etlo, g_etlo);
    SYM(hatth, g_hatth); SYM(hattl, g_hattl);
    SYM(hbnh, g_hbnh); SYM(hbnl, g_hbnl);
    SYM(h2ah, g_h2ah); SYM(h2al, g_h2al);
    bf16 *wq_h, *wq_l, *wk_h, *wk_l, *wv_h, *wv_l, *we_h, *we_l;
    bf16 *woh_h, *woh_l, *woe_h, *woe_l, *w1_h, *w1_l, *w2_h, *w2_l;
    SYM(wq_h, g_wq_h); SYM(wq_l, g_wq_l); SYM(wk_h, g_wk_h); SYM(wk_l, g_wk_l);
    SYM(wv_h, g_wv_h); SYM(wv_l, g_wv_l); SYM(we_h, g_we_h); SYM(we_l, g_we_l);
    SYM(woh_h, g_woh_h); SYM(woh_l, g_woh_l); SYM(woe_h, g_woe_h); SYM(woe_l, g_woe_l);
    SYM(w1_h, g_w1_h); SYM(w1_l, g_w1_l); SYM(w2_h, g_w2_h); SYM(w2_l, g_w2_l);

    float* hout = (float*)d_out;
    float* eout = (float*)d_out + (size_t)NN * DIM;

    cudaFuncSetAttribute(mma_gemmB<1, 0, false, true >, cudaFuncAttributeMaxDynamicSharedMemorySize, SMB_TOTAL);
    cudaFuncSetAttribute(mma_gemmB<0, 1, true,  false>, cudaFuncAttributeMaxDynamicSharedMemorySize, SMB_TOTAL);
    cudaFuncSetAttribute(mma_gemmB<2, 0, false, true >, cudaFuncAttributeMaxDynamicSharedMemorySize, SMB_TOTAL);
    cudaFuncSetAttribute(qkv_gemm, cudaFuncAttributeMaxDynamicSharedMemorySize, SMB_TOTAL);
    cudaFuncSetAttribute(edge_gemm_fused, cudaFuncAttributeMaxDynamicSharedMemorySize, SMB_TOTAL);

    // ---- pre-convert fp32 -> bf16 hi/lo ----
    auto pc = [&](const float* in, bf16* h, bf16* l, long long n) {
        preconv<<<cdiv(n / 4, 256), 256>>>(in, h, l, n);
    };
    pc(x, xhi, xlo, (long long)NN * DIM);
    pc(edge_attr, eahi, ealo, (long long)NE * DIM);
    pc(Wq, wq_h, wq_l, DIM * DIM);
    pc(Wk, wk_h, wk_l, DIM * DIM);
    pc(Wv, wv_h, wv_l, DIM * DIM);
    pc(We, we_h, we_l, DIM * 2 * DIM);
    pc(WOh, woh_h, woh_l, DIM * DIM);
    pc(WOe, woe_h, woe_l, DIM * DIM);
    pc(W1, w1_h, w1_l, DIM * 2 * DIM);
    pc(W2, w2_h, w2_l, 2 * DIM * DIM);

    // init accumulators
    cudaMemsetAsync(wV, 0, (size_t)NN * DIM * sizeof(float));
    cudaMemsetAsync(rowV, 0, (size_t)NN * DIM * sizeof(float));
    cudaMemsetAsync(den, 0, (size_t)NN * NH * sizeof(float));
    cudaMemsetAsync(s1, 0, 2 * DIM * sizeof(float));
    cudaMemsetAsync(s2, 0, 2 * DIM * sizeof(float));
    cudaMemsetAsync(se, 0, 2 * DIM * sizeof(float));

    const int gN = cdiv(NN, 128), gE = cdiv(NE, 128);

    // Q/K/V in one launch (x-tile L2 reuse across the 3 sibling blocks)
    qkv_gemm<<<dim3(3, gN), 256, SMB_TOTAL>>>(xhi, xlo, wq_h, wq_l, wk_h, wk_l,
                                              wv_h, wv_l, bq, bk, bv, Qh, Kh, Vh);

    // fused Ee GEMM + score/logit + exp (max-free softmax; A-tile L2 reuse)
    edge_gemm_fused<<<dim3(2, gE), 256, SMB_TOTAL>>>(eahi, ealo, we_h, we_l, be,
                                                     ei, Aw, Qh, Kh, ethi, etlo, lg);

    // denominator + unnormalized scatter
    edge_scatter<<<cdiv(NE * NH, 256), 256>>>(ei, lg, den, Vh, ethi, etlo, wV, rowV);

    node_fix<<<cdiv(NN * 64, 256), 256>>>(wV, rowV, den, VeRow, log_deg, deg_coef, hatth, hattl);

    // h path: WOh + residual(x) -> v1 with fused stats; BN1 -> hbn pair
    mma_gemmB<1, 0, false, true><<<dim3(1, gN), 256, SMB_TOTAL>>>(
        hatth, hattl, woh_h, woh_l, bOh, x, nullptr, nullptr, v1, nullptr, nullptr, s1, NN, 128, 128);
    bn_apply<true><<<cdiv((long long)NN * 64, 256), 256>>>(v1, nullptr, hbnh, hbnl, NN, s1, g1h, b1h, 1.f / NN);

    // e path: WOe + residual(edge_attr) -> eout with fused stats; BN apply
    mma_gemmB<1, 0, false, true><<<dim3(1, gE), 256, SMB_TOTAL>>>(
        ethi, etlo, woe_h, woe_l, bOe, edge_attr, nullptr, nullptr, eout, nullptr, nullptr, se, NE, 128, 128);
    bn_apply<false><<<cdiv((long long)NE * 64, 256), 256>>>(eout, eout, nullptr, nullptr, NE, se, g1e, b1e, 1.f / NE);

    // FFN: W1(relu) -> h2a pair; W2 + residual(hbn pair) -> v2 with stats; BN2 -> hout
    mma_gemmB<0, 1, true, false><<<dim3(2, gN), 256, SMB_TOTAL>>>(
        hbnh, hbnl, w1_h, w1_l, b1, nullptr, nullptr, nullptr, nullptr, h2ah, h2al, nullptr, NN, 256, 128);
    mma_gemmB<2, 0, false, true><<<dim3(1, gN), 256, SMB_TOTAL>>>(
        h2ah, h2al, w2_h, w2_l, b2, nullptr, hbnh, hbnl, v2, nullptr, nullptr, s2, NN, 128, 256);
    bn_apply<false><<<cdiv((long long)NN * 64, 256), 256>>>(v2, hout, nullptr, nullptr, NN, s2, g2h, b2h, 1.f / NN);
}